// round 1
// baseline (speedup 1.0000x reference)
#include <cuda_runtime.h>
#include <cstdint>

// ---------------------------------------------------------------------------
// VolterraGraphConvLayer: out = relu( X@W0^T + S1@W1^T + S2@W2^T + bias )
//   M[p] = A[p] @ X          (P=3, N=8192, D=256, K=8192)
//   S1   = M0+M1+M2
//   S2   = (S1^2 + M0^2+M1^2+M2^2)/2   (elementwise)
//   bias = b0 + 3*b1 + 6*b2
// TF32 tensor-core path (mma.sync.m16n8k8), fp32 accumulate.
// ---------------------------------------------------------------------------

#define N_NODES 8192
#define DIM     256
#define NPOW    3

// scratch for M[p]  (25 MB, L2-resident)
__device__ __align__(128) float g_M[(size_t)NPOW * N_NODES * DIM];

// ---------------- PTX helpers ----------------
__device__ __forceinline__ uint32_t smem_u32(const void* p) {
    return (uint32_t)__cvta_generic_to_shared(p);
}
__device__ __forceinline__ void cp_async16(uint32_t dst, const void* src) {
    asm volatile("cp.async.cg.shared.global [%0], [%1], 16;\n" :: "r"(dst), "l"(src));
}
__device__ __forceinline__ void cp_commit() { asm volatile("cp.async.commit_group;\n"); }
template <int N> __device__ __forceinline__ void cp_wait() {
    asm volatile("cp.async.wait_group %0;\n" :: "n"(N));
}
__device__ __forceinline__ uint32_t f2tf32(float x) {
    uint32_t r; asm("cvt.rna.tf32.f32 %0, %1;\n" : "=r"(r) : "f"(x)); return r;
}
__device__ __forceinline__ void mma_tf32(float c[4],
                                         uint32_t a0, uint32_t a1, uint32_t a2, uint32_t a3,
                                         uint32_t b0, uint32_t b1) {
    asm volatile(
        "mma.sync.aligned.m16n8k8.row.col.f32.tf32.tf32.f32 "
        "{%0,%1,%2,%3}, {%4,%5,%6,%7}, {%8,%9}, {%0,%1,%2,%3};\n"
        : "+f"(c[0]), "+f"(c[1]), "+f"(c[2]), "+f"(c[3])
        : "r"(a0), "r"(a1), "r"(a2), "r"(a3), "r"(b0), "r"(b1));
}

// ---------------------------------------------------------------------------
// Kernel 1:  M[p] = A[p] @ X
// BM=128 BN=256(=full D) BK=32, 512 threads (4x4 warps), double-buffered cp.async
// grid.x = 3 * (8192/128) = 192
// ---------------------------------------------------------------------------
#define K1_BM 128
#define K1_BK 32
#define AS_STRIDE 36     // 32 + 4 pad  (row bytes = 144 = 9*16, 16B aligned)
#define XS_STRIDE 264    // 256 + 8 pad (row bytes = 1056 = 66*16)
#define K1_AS_STAGE (K1_BM * AS_STRIDE)   // 4608 floats
#define K1_XS_STAGE (K1_BK * XS_STRIDE)   // 8448 floats
#define K1_SMEM_BYTES ((2 * K1_AS_STAGE + 2 * K1_XS_STAGE) * 4)  // 104448

__global__ void __launch_bounds__(512)
volterra_gemm1(const float* __restrict__ A, const float* __restrict__ X) {
    extern __shared__ float smem[];
    float* As = smem;                       // [2][128][36]
    float* Xs = smem + 2 * K1_AS_STAGE;     // [2][32][264]

    const int bx      = blockIdx.x;
    const int p       = bx >> 6;        // /64
    const int rowTile = bx & 63;
    const int row0    = rowTile * K1_BM;
    const float* Ap   = A + (size_t)p * N_NODES * N_NODES;

    const int tid  = threadIdx.x;
    const int wid  = tid >> 5;
    const int lane = tid & 31;
    const int warpRow = (wid >> 2) * 32;   // 4 warp-rows of 32
    const int warpCol = (wid & 3) * 64;    // 4 warp-cols of 64

    float acc[2][8][4];
#pragma unroll
    for (int mt = 0; mt < 2; mt++)
#pragma unroll
        for (int nt = 0; nt < 8; nt++)
#pragma unroll
            for (int i = 0; i < 4; i++) acc[mt][nt][i] = 0.f;

    const int NT = N_NODES / K1_BK;  // 256 k-tiles

    // ---- async tile loader ----
    auto issue = [&](int kt, int stage) {
        const int k0 = kt * K1_BK;
        float* as = As + stage * K1_AS_STAGE;
        float* xs = Xs + stage * K1_XS_STAGE;
        // A tile: 128 x 32 = 1024 float4
#pragma unroll
        for (int i = 0; i < 2; i++) {
            int idx = tid + i * 512;
            int r = idx >> 3, c4 = idx & 7;
            cp_async16(smem_u32(&as[r * AS_STRIDE + c4 * 4]),
                       Ap + (size_t)(row0 + r) * N_NODES + k0 + c4 * 4);
        }
        // X tile: 32 x 256 = 2048 float4
#pragma unroll
        for (int i = 0; i < 4; i++) {
            int idx = tid + i * 512;
            int k = idx >> 6, c4 = idx & 63;
            cp_async16(smem_u32(&xs[k * XS_STRIDE + c4 * 4]),
                       X + (size_t)(k0 + k) * DIM + c4 * 4);
        }
        cp_commit();
    };

    issue(0, 0);

    for (int kt = 0; kt < NT; kt++) {
        const int stage = kt & 1;
        if (kt + 1 < NT) { issue(kt + 1, stage ^ 1); cp_wait<1>(); }
        else             { cp_wait<0>(); }
        __syncthreads();

        const float* as = As + stage * K1_AS_STAGE;
        const float* xs = Xs + stage * K1_XS_STAGE;

#pragma unroll
        for (int k8 = 0; k8 < 4; k8++) {
            const int kb = k8 * 8;
            uint32_t af[2][4];
#pragma unroll
            for (int mt = 0; mt < 2; mt++) {
                int r = warpRow + mt * 16 + (lane >> 2);
                int c = kb + (lane & 3);
                af[mt][0] = f2tf32(as[r * AS_STRIDE + c]);
                af[mt][1] = f2tf32(as[(r + 8) * AS_STRIDE + c]);
                af[mt][2] = f2tf32(as[r * AS_STRIDE + c + 4]);
                af[mt][3] = f2tf32(as[(r + 8) * AS_STRIDE + c + 4]);
            }
#pragma unroll
            for (int nt = 0; nt < 8; nt++) {
                int n = warpCol + nt * 8 + (lane >> 2);
                int k = kb + (lane & 3);
                uint32_t b0 = f2tf32(xs[k * XS_STRIDE + n]);
                uint32_t b1 = f2tf32(xs[(k + 4) * XS_STRIDE + n]);
                mma_tf32(acc[0][nt], af[0][0], af[0][1], af[0][2], af[0][3], b0, b1);
                mma_tf32(acc[1][nt], af[1][0], af[1][1], af[1][2], af[1][3], b0, b1);
            }
        }
        __syncthreads();
    }

    // ---- store M[p] tile ----
    float* Mout = g_M + (size_t)p * N_NODES * DIM;
#pragma unroll
    for (int mt = 0; mt < 2; mt++) {
#pragma unroll
        for (int nt = 0; nt < 8; nt++) {
            int r = row0 + warpRow + mt * 16 + (lane >> 2);
            int c = warpCol + nt * 8 + 2 * (lane & 3);
            float2 v0 = make_float2(acc[mt][nt][0], acc[mt][nt][1]);
            float2 v1 = make_float2(acc[mt][nt][2], acc[mt][nt][3]);
            *(float2*)&Mout[(size_t)r * DIM + c]       = v0;
            *(float2*)&Mout[(size_t)(r + 8) * DIM + c] = v1;
        }
    }
}

// ---------------------------------------------------------------------------
// Kernel 2:  out = relu( [X | S1 | S2] @ [W0 | W1 | W2]^T + bias )
// Logical K = 768 in 24 chunks of 32. S1/S2 chunks computed on the fly from
// g_M (all L2 hits). BM=64, BN=256, 256 threads (2x4 warps).  grid.x = 128
// ---------------------------------------------------------------------------
__global__ void __launch_bounds__(256)
volterra_gemm2(const float* __restrict__ X, const float* __restrict__ W,
               const float* __restrict__ bvec, float* __restrict__ out) {
    __shared__ float Ts[64][AS_STRIDE];    // 64 x (32+4)
    __shared__ float Ws[256][AS_STRIDE];   // 256 x (32+4)

    const int row0 = blockIdx.x * 64;
    const int tid  = threadIdx.x;
    const int wid  = tid >> 5;
    const int lane = tid & 31;
    const int warpRow = (wid >> 2) * 32;   // 2 warp-rows of 32
    const int warpCol = (wid & 3) * 64;    // 4 warp-cols of 64

    float acc[2][8][4];
#pragma unroll
    for (int mt = 0; mt < 2; mt++)
#pragma unroll
        for (int nt = 0; nt < 8; nt++)
#pragma unroll
            for (int i = 0; i < 4; i++) acc[mt][nt][i] = 0.f;

    const size_t MSZ = (size_t)N_NODES * DIM;

    for (int kc = 0; kc < 24; kc++) {
        const int r  = kc >> 3;          // which order (0,1,2)
        const int k0 = (kc & 7) * 32;    // k offset within 256

        // ---- build T chunk: 64 x 32 = 512 float4, 2 per thread ----
#pragma unroll
        for (int i = 0; i < 2; i++) {
            int idx = tid + i * 256;
            int rr = idx >> 3, c4 = idx & 7;
            size_t g = (size_t)(row0 + rr) * DIM + k0 + c4 * 4;
            float4 v;
            if (r == 0) {
                v = *(const float4*)&X[g];
            } else {
                float4 m0 = *(const float4*)&g_M[g];
                float4 m1 = *(const float4*)&g_M[MSZ + g];
                float4 m2 = *(const float4*)&g_M[2 * MSZ + g];
                if (r == 1) {
                    v.x = m0.x + m1.x + m2.x;  v.y = m0.y + m1.y + m2.y;
                    v.z = m0.z + m1.z + m2.z;  v.w = m0.w + m1.w + m2.w;
                } else {
                    float s, q;
                    s = m0.x + m1.x + m2.x; q = m0.x*m0.x + m1.x*m1.x + m2.x*m2.x; v.x = 0.5f*(s*s + q);
                    s = m0.y + m1.y + m2.y; q = m0.y*m0.y + m1.y*m1.y + m2.y*m2.y; v.y = 0.5f*(s*s + q);
                    s = m0.z + m1.z + m2.z; q = m0.z*m0.z + m1.z*m1.z + m2.z*m2.z; v.z = 0.5f*(s*s + q);
                    s = m0.w + m1.w + m2.w; q = m0.w*m0.w + m1.w*m1.w + m2.w*m2.w; v.w = 0.5f*(s*s + q);
                }
            }
            *(float4*)&Ts[rr][c4 * 4] = v;
        }
        // ---- W_r chunk: 256 x 32 = 2048 float4, 8 per thread ----
        const float* Wr = W + (size_t)r * DIM * DIM;
#pragma unroll
        for (int i = 0; i < 8; i++) {
            int idx = tid + i * 256;
            int d = idx >> 3, c4 = idx & 7;
            *(float4*)&Ws[d][c4 * 4] = *(const float4*)&Wr[(size_t)d * DIM + k0 + c4 * 4];
        }
        __syncthreads();

#pragma unroll
        for (int k8 = 0; k8 < 4; k8++) {
            const int kb = k8 * 8;
            uint32_t af[2][4];
#pragma unroll
            for (int mt = 0; mt < 2; mt++) {
                int rr = warpRow + mt * 16 + (lane >> 2);
                int c = kb + (lane & 3);
                af[mt][0] = f2tf32(Ts[rr][c]);
                af[mt][1] = f2tf32(Ts[rr + 8][c]);
                af[mt][2] = f2tf32(Ts[rr][c + 4]);
                af[mt][3] = f2tf32(Ts[rr + 8][c + 4]);
            }
#pragma unroll
            for (int nt = 0; nt < 8; nt++) {
                int d = warpCol + nt * 8 + (lane >> 2);
                int k = kb + (lane & 3);
                uint32_t b0 = f2tf32(Ws[d][k]);
                uint32_t b1 = f2tf32(Ws[d][k + 4]);
                mma_tf32(acc[0][nt], af[0][0], af[0][1], af[0][2], af[0][3], b0, b1);
                mma_tf32(acc[1][nt], af[1][0], af[1][1], af[1][2], af[1][3], b0, b1);
            }
        }
        __syncthreads();
    }

    // ---- bias + relu + store ----
#pragma unroll
    for (int nt = 0; nt < 8; nt++) {
        int c  = warpCol + nt * 8 + 2 * (lane & 3);
        float bias0 = bvec[c]     + 3.f * bvec[DIM + c]     + 6.f * bvec[2 * DIM + c];
        float bias1 = bvec[c + 1] + 3.f * bvec[DIM + c + 1] + 6.f * bvec[2 * DIM + c + 1];
#pragma unroll
        for (int mt = 0; mt < 2; mt++) {
            int rr = row0 + warpRow + mt * 16 + (lane >> 2);
            float2 v0 = make_float2(fmaxf(acc[mt][nt][0] + bias0, 0.f),
                                    fmaxf(acc[mt][nt][1] + bias1, 0.f));
            float2 v1 = make_float2(fmaxf(acc[mt][nt][2] + bias0, 0.f),
                                    fmaxf(acc[mt][nt][3] + bias1, 0.f));
            *(float2*)&out[(size_t)rr * DIM + c]       = v0;
            *(float2*)&out[(size_t)(rr + 8) * DIM + c] = v1;
        }
    }
}

// ---------------------------------------------------------------------------
extern "C" void kernel_launch(void* const* d_in, const int* in_sizes, int n_in,
                              void* d_out, int out_size) {
    const float *X = nullptr, *A = nullptr, *W = nullptr, *b = nullptr;
    for (int i = 0; i < n_in; i++) {
        long long s = in_sizes[i];
        if      (s == (long long)N_NODES * DIM)            X = (const float*)d_in[i];
        else if (s == (long long)NPOW * N_NODES * N_NODES) A = (const float*)d_in[i];
        else if (s == (long long)NPOW * DIM * DIM)         W = (const float*)d_in[i];
        else if (s == (long long)NPOW * DIM)               b = (const float*)d_in[i];
    }

    cudaFuncSetAttribute(volterra_gemm1,
                         cudaFuncAttributeMaxDynamicSharedMemorySize, K1_SMEM_BYTES);

    volterra_gemm1<<<NPOW * (N_NODES / K1_BM), 512, K1_SMEM_BYTES>>>(A, X);
    volterra_gemm2<<<N_NODES / 64, 256>>>(X, W, b, (float*)d_out);
}